// round 13
// baseline (speedup 1.0000x reference)
#include <cuda_runtime.h>
#include <cstdint>

#define CHN 128
#define HH  128
#define WW  128
#define TH  4
#define CSPLIT 4
#define CPB (CHN/CSPLIT)   // 32 channels per block

#define SMEM_BYTES (25 * 256 * 8)   // per-thread 25 packed ksa taps, [tap][tid] layout

typedef unsigned long long ull;

__constant__ float c_w[CHN * 25];
__constant__ float c_b[CHN];

__device__ __forceinline__ ull pack2(float lo, float hi) {
    ull r; asm("mov.b64 %0, {%1, %2};" : "=l"(r) : "f"(lo), "f"(hi)); return r;
}
__device__ __forceinline__ void unpack2(ull v, float& lo, float& hi) {
    asm("mov.b64 {%0, %1}, %2;" : "=f"(lo), "=f"(hi) : "l"(v));
}
__device__ __forceinline__ ull mul2(ull a, ull b) {
    ull d; asm("mul.rn.f32x2 %0, %1, %2;" : "=l"(d) : "l"(a), "l"(b)); return d;
}
__device__ __forceinline__ ull fma2(ull a, ull b, ull c) {
    ull d; asm("fma.rn.f32x2 %0, %1, %2, %3;" : "=l"(d) : "l"(a), "l"(b), "l"(c)); return d;
}
__device__ __forceinline__ ull add2(ull a, ull b) {
    ull d; asm("add.rn.f32x2 %0, %1, %2;" : "=l"(d) : "l"(a), "l"(b)); return d;
}
__device__ __forceinline__ ull dup2(float v) {
    ull r; asm("mov.b64 %0, {%1, %1};" : "=l"(r) : "f"(v)); return r;
}

__global__ __launch_bounds__(256, 4)
void dwconv_ksa_kernel(const float* __restrict__ x,
                       const float* __restrict__ ksa,
                       float* __restrict__ out)
{
    extern __shared__ ull kks[];           // [25][256]: tap-major, lane-contiguous

    const int tx = threadIdx.x;            // 0..63 -> w-pair
    const int ty = threadIdx.y;            // 0..3
    const int tid = ty * 64 + tx;
    const int h0 = blockIdx.x * TH;
    const int n  = blockIdx.y;
    const int c0 = blockIdx.z * CPB;

    const int h  = h0 + ty;
    const int w0 = tx * 2;

    // ---- ksa for this pixel pair -> masked, packed, staged into SMEM ----
    {
        const float* ksabase = ksa + ((size_t)(n * 25) * HH + h) * WW + w0;
        #pragma unroll
        for (int t = 0; t < 25; t++) {
            float2 v = *(const float2*)(ksabase + (size_t)t * HH * WW);
            const int i = t / 5, j = t % 5;
            const int r = h + i - 2;
            const bool rok = (r >= 0) && (r < HH);
            const int cA = w0 + j - 2;
            const int cB = cA + 1;
            v.x = (rok && cA >= 0 && cA < WW) ? v.x : 0.0f;
            v.y = (rok && cB >= 0 && cB < WW) ? v.y : 0.0f;
            kks[t * 256 + tid] = pack2(v.x, v.y);
        }
    }
    __syncthreads();

    // clamped row offsets (garbage rows masked by kk==0)
    int rowoff[5];
    #pragma unroll
    for (int i = 0; i < 5; i++) {
        int r = h + i - 2;
        r = r < 0 ? 0 : (r > HH - 1 ? HH - 1 : r);
        rowoff[i] = r * WW;
    }
    const int e0 = (w0 - 2 < 0) ? 0 : (w0 - 2);
    const int e2 = (w0 + 2 > WW - 2) ? (WW - 2) : (w0 + 2);

    const float* xc   = x   + (size_t)(n * CHN + c0) * HH * WW;
    float*       outp = out + ((size_t)(n * CHN + c0) * HH + h) * WW + w0;
    const ull*   kkt  = kks + tid;         // this thread's taps, stride 256

    #pragma unroll 1
    for (int cl = 0; cl < CPB; ++cl) {
        const float* wc = c_w + (c0 + cl) * 25;

        ull accA = dup2(c_b[c0 + cl]);     // acc init = {bias,bias}
        ull accB = 0ULL;

        #pragma unroll
        for (int i = 0; i < 5; i++) {
            const float* row = xc + rowoff[i];
            const float2 A = *(const float2*)(row + e0);
            const float2 B = *(const float2*)(row + w0);
            const float2 C = *(const float2*)(row + e2);

            accA = fma2(mul2(kkt[(i*5+0)*256], dup2(wc[i*5+0])), pack2(A.x, A.y), accA);
            accB = fma2(mul2(kkt[(i*5+1)*256], dup2(wc[i*5+1])), pack2(A.y, B.x), accB);
            accA = fma2(mul2(kkt[(i*5+2)*256], dup2(wc[i*5+2])), pack2(B.x, B.y), accA);
            accB = fma2(mul2(kkt[(i*5+3)*256], dup2(wc[i*5+3])), pack2(B.y, C.x), accB);
            accA = fma2(mul2(kkt[(i*5+4)*256], dup2(wc[i*5+4])), pack2(C.x, C.y), accA);
        }

        float a0, a1;
        unpack2(add2(accA, accB), a0, a1);
        *(float2*)outp = make_float2(a0, a1);

        xc += HH * WW;
        outp += HH * WW;
    }
}

extern "C" void kernel_launch(void* const* d_in, const int* in_sizes, int n_in,
                              void* d_out, int out_size)
{
    const float* x   = (const float*)d_in[0];
    const float* ksa = (const float*)d_in[1];
    const float* w   = (const float*)d_in[2];
    const float* b   = (const float*)d_in[3];
    float* out = (float*)d_out;

    const int n_batch = in_sizes[0] / (CHN * HH * WW);   // 4

    cudaMemcpyToSymbolAsync(c_w, w, CHN * 25 * sizeof(float), 0, cudaMemcpyDeviceToDevice);
    cudaMemcpyToSymbolAsync(c_b, b, CHN * sizeof(float), 0, cudaMemcpyDeviceToDevice);

    // opt-in to >48KB dynamic smem (state change only; capture-safe, no alloc)
    cudaFuncSetAttribute(dwconv_ksa_kernel,
                         cudaFuncAttributeMaxDynamicSharedMemorySize, SMEM_BYTES);

    dim3 block(64, TH);
    dim3 grid(HH / TH, n_batch, CSPLIT);
    dwconv_ksa_kernel<<<grid, block, SMEM_BYTES>>>(x, ksa, out);
}

// round 15
// speedup vs baseline: 1.2926x; 1.2926x over previous
#include <cuda_runtime.h>
#include <cstdint>

#define CHN 128
#define HH  128
#define WW  128
#define TH  4
#define CSPLIT 4
#define CPB (CHN/CSPLIT)   // 32 channels per block

#define NREG  10           // taps 0..9 in registers
#define NSMEM 15           // taps 10..24 in shared memory

typedef unsigned long long ull;

__constant__ float c_w[CHN * 25];
__constant__ float c_b[CHN];

__device__ __forceinline__ ull pack2(float lo, float hi) {
    ull r; asm("mov.b64 %0, {%1, %2};" : "=l"(r) : "f"(lo), "f"(hi)); return r;
}
__device__ __forceinline__ void unpack2(ull v, float& lo, float& hi) {
    asm("mov.b64 {%0, %1}, %2;" : "=f"(lo), "=f"(hi) : "l"(v));
}
__device__ __forceinline__ ull mul2(ull a, ull b) {
    ull d; asm("mul.rn.f32x2 %0, %1, %2;" : "=l"(d) : "l"(a), "l"(b)); return d;
}
__device__ __forceinline__ ull fma2(ull a, ull b, ull c) {
    ull d; asm("fma.rn.f32x2 %0, %1, %2, %3;" : "=l"(d) : "l"(a), "l"(b), "l"(c)); return d;
}
__device__ __forceinline__ ull add2(ull a, ull b) {
    ull d; asm("add.rn.f32x2 %0, %1, %2;" : "=l"(d) : "l"(a), "l"(b)); return d;
}
__device__ __forceinline__ ull dup2(float v) {
    ull r; asm("mov.b64 %0, {%1, %1};" : "=l"(r) : "f"(v)); return r;
}

__global__ __launch_bounds__(256, 3)
void dwconv_ksa_kernel(const float* __restrict__ x,
                       const float* __restrict__ ksa,
                       float* __restrict__ out)
{
    __shared__ ull kks[NSMEM * 256];       // taps 10..24, [tap][tid], conflict-free LDS.64

    const int tx = threadIdx.x;            // 0..63 -> w-pair
    const int ty = threadIdx.y;            // 0..3
    const int tid = ty * 64 + tx;
    const int h0 = blockIdx.x * TH;
    const int n  = blockIdx.y;
    const int c0 = blockIdx.z * CPB;

    const int h  = h0 + ty;
    const int w0 = tx * 2;

    // ---- ksa -> masked packed taps: 0..9 regs, 10..24 smem ----
    ull kkr[NREG];
    {
        const float* ksabase = ksa + ((size_t)(n * 25) * HH + h) * WW + w0;
        #pragma unroll
        for (int t = 0; t < 25; t++) {
            float2 v = *(const float2*)(ksabase + (size_t)t * HH * WW);
            const int i = t / 5, j = t % 5;
            const int r = h + i - 2;
            const bool rok = (r >= 0) && (r < HH);
            const int cA = w0 + j - 2;
            const int cB = cA + 1;
            v.x = (rok && cA >= 0 && cA < WW) ? v.x : 0.0f;
            v.y = (rok && cB >= 0 && cB < WW) ? v.y : 0.0f;
            if (t < NREG) kkr[t] = pack2(v.x, v.y);
            else          kks[(t - NREG) * 256 + tid] = pack2(v.x, v.y);
        }
    }
    __syncthreads();

    // clamped row offsets (garbage rows masked by kk==0)
    int rowoff[5];
    #pragma unroll
    for (int i = 0; i < 5; i++) {
        int r = h + i - 2;
        r = r < 0 ? 0 : (r > HH - 1 ? HH - 1 : r);
        rowoff[i] = r * WW;
    }
    const int e0 = (w0 - 2 < 0) ? 0 : (w0 - 2);
    const int e2 = (w0 + 2 > WW - 2) ? (WW - 2) : (w0 + 2);

    const float* xn   = x   + (size_t)(n * CHN + c0) * HH * WW;
    float*       outp = out + ((size_t)(n * CHN + c0) * HH + h) * WW + w0;

    // 2 channels per iteration: independent fma chains; kk taps shared by both.
    #pragma unroll 1
    for (int cp = 0; cp < CPB / 2; ++cp) {
        const int ca = 2 * cp;
        const float* xa = xn + (size_t)ca * HH * WW;
        const float* xb = xa + HH * WW;
        const float* wca = c_w + (c0 + ca) * 25;
        const float* wcb = wca + 25;

        ull aA = dup2(c_b[c0 + ca]);       // acc init = {bias,bias}
        ull aB = 0ULL;
        ull bA = dup2(c_b[c0 + ca + 1]);
        ull bB = 0ULL;

        #pragma unroll
        for (int i = 0; i < 5; i++) {
            const float* ra = xa + rowoff[i];
            const float* rb = xb + rowoff[i];
            const float2 A0 = *(const float2*)(ra + e0);
            const float2 B0 = *(const float2*)(ra + w0);
            const float2 C0 = *(const float2*)(ra + e2);
            const float2 A1 = *(const float2*)(rb + e0);
            const float2 B1 = *(const float2*)(rb + w0);
            const float2 C1 = *(const float2*)(rb + e2);

            // row taps: registers for i<2, shared memory for i>=2 (static per unrolled i)
            ull k0, k1, k2, k3, k4;
            if (i < 2) {
                k0 = kkr[i*5+0]; k1 = kkr[i*5+1]; k2 = kkr[i*5+2];
                k3 = kkr[i*5+3]; k4 = kkr[i*5+4];
            } else {
                const ull* ks = kks + (i*5 - NREG) * 256 + tid;
                k0 = ks[0*256]; k1 = ks[1*256]; k2 = ks[2*256];
                k3 = ks[3*256]; k4 = ks[4*256];
            }

            const ull q00 = pack2(A0.x, A0.y);
            const ull q01 = pack2(A0.y, B0.x);
            const ull q02 = pack2(B0.x, B0.y);
            const ull q03 = pack2(B0.y, C0.x);
            const ull q04 = pack2(C0.x, C0.y);
            const ull q10 = pack2(A1.x, A1.y);
            const ull q11 = pack2(A1.y, B1.x);
            const ull q12 = pack2(B1.x, B1.y);
            const ull q13 = pack2(B1.y, C1.x);
            const ull q14 = pack2(C1.x, C1.y);

            aA = fma2(mul2(k0, dup2(wca[i*5+0])), q00, aA);
            bA = fma2(mul2(k0, dup2(wcb[i*5+0])), q10, bA);
            aB = fma2(mul2(k1, dup2(wca[i*5+1])), q01, aB);
            bB = fma2(mul2(k1, dup2(wcb[i*5+1])), q11, bB);
            aA = fma2(mul2(k2, dup2(wca[i*5+2])), q02, aA);
            bA = fma2(mul2(k2, dup2(wcb[i*5+2])), q12, bA);
            aB = fma2(mul2(k3, dup2(wca[i*5+3])), q03, aB);
            bB = fma2(mul2(k3, dup2(wcb[i*5+3])), q13, bB);
            aA = fma2(mul2(k4, dup2(wca[i*5+4])), q04, aA);
            bA = fma2(mul2(k4, dup2(wcb[i*5+4])), q14, bA);
        }

        ull ra2 = add2(aA, aB);
        ull rb2 = add2(bA, bB);
        float a0, a1, b0v, b1v;
        unpack2(ra2, a0, a1);
        unpack2(rb2, b0v, b1v);
        *(float2*)(outp + (size_t)ca * HH * WW)       = make_float2(a0, a1);
        *(float2*)(outp + (size_t)(ca + 1) * HH * WW) = make_float2(b0v, b1v);
    }
}

extern "C" void kernel_launch(void* const* d_in, const int* in_sizes, int n_in,
                              void* d_out, int out_size)
{
    const float* x   = (const float*)d_in[0];
    const float* ksa = (const float*)d_in[1];
    const float* w   = (const float*)d_in[2];
    const float* b   = (const float*)d_in[3];
    float* out = (float*)d_out;

    const int n_batch = in_sizes[0] / (CHN * HH * WW);   // 4

    cudaMemcpyToSymbolAsync(c_w, w, CHN * 25 * sizeof(float), 0, cudaMemcpyDeviceToDevice);
    cudaMemcpyToSymbolAsync(c_b, b, CHN * sizeof(float), 0, cudaMemcpyDeviceToDevice);

    dim3 block(64, TH);
    dim3 grid(HH / TH, n_batch, CSPLIT);
    dwconv_ksa_kernel<<<grid, block>>>(x, ksa, out);
}

// round 16
// speedup vs baseline: 2.4304x; 1.8802x over previous
#include <cuda_runtime.h>
#include <cstdint>

#define CHN 128
#define HH  128
#define WW  128
#define TH  4
#define CSPLIT 2
#define CPB 64

typedef unsigned long long ull;

__device__ __forceinline__ ull pack2(float lo, float hi) {
    ull r; asm("mov.b64 %0, {%1, %2};" : "=l"(r) : "f"(lo), "f"(hi)); return r;
}
__device__ __forceinline__ void unpack2(ull v, float& lo, float& hi) {
    asm("mov.b64 {%0, %1}, %2;" : "=f"(lo), "=f"(hi) : "l"(v));
}
__device__ __forceinline__ ull mul2(ull a, ull b) {
    ull d; asm("mul.rn.f32x2 %0, %1, %2;" : "=l"(d) : "l"(a), "l"(b)); return d;
}
__device__ __forceinline__ ull fma2(ull a, ull b, ull c) {
    ull d; asm("fma.rn.f32x2 %0, %1, %2, %3;" : "=l"(d) : "l"(a), "l"(b), "l"(c)); return d;
}
__device__ __forceinline__ ull add2(ull a, ull b) {
    ull d; asm("add.rn.f32x2 %0, %1, %2;" : "=l"(d) : "l"(a), "l"(b)); return d;
}
// streaming (evict-first) 8B store
__device__ __forceinline__ void stcs2(float* p, float lo, float hi) {
    asm volatile("st.global.cs.v2.f32 [%0], {%1, %2};" :: "l"(p), "f"(lo), "f"(hi) : "memory");
}

__global__ __launch_bounds__(256, 2)
void dwconv_ksa_kernel(const float* __restrict__ x,
                       const float* __restrict__ ksa,
                       const float* __restrict__ w,
                       const float* __restrict__ b,
                       float* __restrict__ out)
{
    // grid: (H/TH, N, CSPLIT); block: (64, TH)
    const int tx = threadIdx.x;            // 0..63 -> w-pair
    const int ty = threadIdx.y;            // 0..3
    const int tid = ty * 64 + tx;
    const int h0 = blockIdx.x * TH;
    const int n  = blockIdx.y;
    const int c0 = blockIdx.z * CPB;

    __shared__ float2 ws2[CPB * 25];       // {w,w} duplicated pairs
    __shared__ float2 bs2[CPB];            // {b,b}

    for (int i = tid; i < CPB * 25; i += 256) {
        float wv = w[c0 * 25 + i];
        ws2[i] = make_float2(wv, wv);
    }
    if (tid < CPB) {
        float bv = b[c0 + tid];
        bs2[tid] = make_float2(bv, bv);
    }

    const int h  = h0 + ty;
    const int w0 = tx * 2;

    // ---- ksa for this pixel pair -> packed registers, boundary masks folded ----
    ull kk2[25];
    const float* ksabase = ksa + ((size_t)(n * 25) * HH + h) * WW + w0;
    #pragma unroll
    for (int t = 0; t < 25; t++) {
        float2 v = *(const float2*)(ksabase + (size_t)t * HH * WW);
        const int i = t / 5, j = t % 5;
        const int r = h + i - 2;
        const bool rok = (r >= 0) && (r < HH);
        const int cA = w0 + j - 2;
        const int cB = cA + 1;
        v.x = (rok && cA >= 0 && cA < WW) ? v.x : 0.0f;
        v.y = (rok && cB >= 0 && cB < WW) ? v.y : 0.0f;
        kk2[t] = pack2(v.x, v.y);
    }

    // clamped row offsets (garbage rows masked by kk==0)
    int rowoff[5];
    #pragma unroll
    for (int i = 0; i < 5; i++) {
        int r = h + i - 2;
        r = r < 0 ? 0 : (r > HH - 1 ? HH - 1 : r);
        rowoff[i] = r * WW;
    }
    const int e0 = (w0 - 2 < 0) ? 0 : (w0 - 2);
    const int e2 = (w0 + 2 > WW - 2) ? (WW - 2) : (w0 + 2);

    __syncthreads();

    const float* xn   = x   + (size_t)(n * CHN + c0) * HH * WW;
    float*       outp = out + ((size_t)(n * CHN + c0) * HH + h) * WW + w0;

    // 2 channels per iteration; unroll 2 -> 4 channels of load MLP in flight
    #pragma unroll 2
    for (int cp = 0; cp < CPB / 2; ++cp) {
        const int ca = 2 * cp;
        const float* xa = xn + (size_t)ca * HH * WW;
        const float* xb = xa + HH * WW;
        const ull* wqa = (const ull*)ws2 + ca * 25;
        const ull* wqb = wqa + 25;

        ull aA = *((const ull*)bs2 + ca);      // acc init = {bias,bias}
        ull aB = 0ULL;
        ull bA = *((const ull*)bs2 + ca + 1);
        ull bB = 0ULL;

        #pragma unroll
        for (int i = 0; i < 5; i++) {
            const float* ra = xa + rowoff[i];
            const float* rb = xb + rowoff[i];
            const float2 A0 = *(const float2*)(ra + e0);
            const float2 B0 = *(const float2*)(ra + w0);
            const float2 C0 = *(const float2*)(ra + e2);
            const float2 A1 = *(const float2*)(rb + e0);
            const float2 B1 = *(const float2*)(rb + w0);
            const float2 C1 = *(const float2*)(rb + e2);

            const ull q00 = pack2(A0.x, A0.y);
            const ull q01 = pack2(A0.y, B0.x);
            const ull q02 = pack2(B0.x, B0.y);
            const ull q03 = pack2(B0.y, C0.x);
            const ull q04 = pack2(C0.x, C0.y);
            const ull q10 = pack2(A1.x, A1.y);
            const ull q11 = pack2(A1.y, B1.x);
            const ull q12 = pack2(B1.x, B1.y);
            const ull q13 = pack2(B1.y, C1.x);
            const ull q14 = pack2(C1.x, C1.y);

            aA = fma2(mul2(kk2[i*5+0], wqa[i*5+0]), q00, aA);
            bA = fma2(mul2(kk2[i*5+0], wqb[i*5+0]), q10, bA);
            aB = fma2(mul2(kk2[i*5+1], wqa[i*5+1]), q01, aB);
            bB = fma2(mul2(kk2[i*5+1], wqb[i*5+1]), q11, bB);
            aA = fma2(mul2(kk2[i*5+2], wqa[i*5+2]), q02, aA);
            bA = fma2(mul2(kk2[i*5+2], wqb[i*5+2]), q12, bA);
            aB = fma2(mul2(kk2[i*5+3], wqa[i*5+3]), q03, aB);
            bB = fma2(mul2(kk2[i*5+3], wqb[i*5+3]), q13, bB);
            aA = fma2(mul2(kk2[i*5+4], wqa[i*5+4]), q04, aA);
            bA = fma2(mul2(kk2[i*5+4], wqb[i*5+4]), q14, bA);
        }

        ull ra = add2(aA, aB);
        ull rb = add2(bA, bB);
        float a0, a1, b0v, b1v;
        unpack2(ra, a0, a1);
        unpack2(rb, b0v, b1v);
        stcs2(outp + (size_t)ca * HH * WW,       a0,  a1);
        stcs2(outp + (size_t)(ca + 1) * HH * WW, b0v, b1v);
    }
}

extern "C" void kernel_launch(void* const* d_in, const int* in_sizes, int n_in,
                              void* d_out, int out_size)
{
    const float* x   = (const float*)d_in[0];
    const float* ksa = (const float*)d_in[1];
    const float* w   = (const float*)d_in[2];
    const float* b   = (const float*)d_in[3];
    float* out = (float*)d_out;

    const int n_batch = in_sizes[0] / (CHN * HH * WW);   // 4

    dim3 block(64, TH);
    dim3 grid(HH / TH, n_batch, CSPLIT);
    dwconv_ksa_kernel<<<grid, block>>>(x, ksa, w, b, out);
}